// round 1
// baseline (speedup 1.0000x reference)
#include <cuda_runtime.h>
#include <math.h>

#define N_NODES 50000
#define N_EDGES 800000
#define F 128
#define NF (N_NODES * F)
#define GSZ (256 * 128)   // one gate weight matrix [2F, F]

// ---------------- static device scratch (no allocs allowed) ----------------
__device__ float g_S1[N_NODES * 256];   // [S_r | S_u]    self-projections
__device__ float g_Yn1[N_NODES * 256];  // [Yn_r | Yn_u]  neighbor-projections
__device__ float g_AGG1[N_NODES * 256]; // aggregated neighbor terms r,u
__device__ float g_S2[N_NODES * 128];   // S_c
__device__ float g_Yn2[N_NODES * 128];  // Yn_c
__device__ float g_AGG2[N_NODES * 128]; // aggregated neighbor term c
__device__ float g_RH[N_NODES * 128];   // r * h
__device__ float g_U[N_NODES * 128];    // u gate

// ---------------- utility ----------------
__global__ void zero_kernel(float* __restrict__ p, int n4) {
    int i = blockIdx.x * blockDim.x + threadIdx.x;
    if (i < n4) ((float4*)p)[i] = make_float4(0.f, 0.f, 0.f, 0.f);
}

__device__ __forceinline__ float sigmoidf_(float x) {
    return 1.0f / (1.0f + expf(-x));
}

// ---------------- SGEMM: C = concat(A0,A1) @ B  ----------------
// A0, A1: [M,128] row-major (concatenated along K -> K=256)
// B blocks: by < half -> Bself + by*GSZ, writes Cself at col by*128
//           else       -> Bneigh + (by-half)*GSZ, writes Cneigh at col (by-half)*128
// Tiles: 128x128, BK=16, 256 threads, 8x8 per thread.
__global__ void __launch_bounds__(256, 2) gemm_cat(
    const float* __restrict__ A0, const float* __restrict__ A1,
    const float* __restrict__ Bself, const float* __restrict__ Bneigh,
    int half, float* __restrict__ Cself, float* __restrict__ Cneigh, int ldc)
{
    const int M = N_NODES;
    __shared__ float As[16][128];
    __shared__ float Bs[16][128];

    int m0 = blockIdx.x * 128;
    int by = blockIdx.y;
    const float* Bp;
    float* Cp;
    int colOff;
    if (by < half) { Bp = Bself + (size_t)by * GSZ;          Cp = Cself;  colOff = by * 128; }
    else           { Bp = Bneigh + (size_t)(by - half) * GSZ; Cp = Cneigh; colOff = (by - half) * 128; }

    int tid = threadIdx.x;
    int ty = tid >> 4, tx = tid & 15;

    float acc[8][8];
#pragma unroll
    for (int i = 0; i < 8; i++)
#pragma unroll
        for (int j = 0; j < 8; j++) acc[i][j] = 0.f;

    for (int k0 = 0; k0 < 256; k0 += 16) {
        const float* A = (k0 < 128) ? A0 : A1;
        int kk0 = k0 & 127;
        // load A tile 128x16 (transposed into As[k][m])
#pragma unroll
        for (int c0 = 0; c0 < 2; c0++) {
            int c = tid + c0 * 256;       // 0..511 float4 chunks
            int row = c >> 2;             // 0..127
            int kc = (c & 3) * 4;         // 0,4,8,12
            int gr = m0 + row;
            float4 v = make_float4(0.f, 0.f, 0.f, 0.f);
            if (gr < M) v = *(const float4*)(A + (size_t)gr * 128 + kk0 + kc);
            As[kc + 0][row] = v.x; As[kc + 1][row] = v.y;
            As[kc + 2][row] = v.z; As[kc + 3][row] = v.w;
        }
        // load B tile 16x128
#pragma unroll
        for (int c0 = 0; c0 < 2; c0++) {
            int c = tid + c0 * 256;
            int krow = c >> 5;            // 0..15
            int ncol = (c & 31) * 4;      // 0..124
            float4 v = *(const float4*)(Bp + (size_t)(k0 + krow) * 128 + ncol);
            *(float4*)&Bs[krow][ncol] = v;
        }
        __syncthreads();
#pragma unroll
        for (int kk = 0; kk < 16; kk++) {
            float a[8], b[8];
#pragma unroll
            for (int i = 0; i < 8; i++) a[i] = As[kk][ty * 8 + i];
#pragma unroll
            for (int j = 0; j < 8; j++) b[j] = Bs[kk][tx * 8 + j];
#pragma unroll
            for (int i = 0; i < 8; i++)
#pragma unroll
                for (int j = 0; j < 8; j++) acc[i][j] = fmaf(a[i], b[j], acc[i][j]);
        }
        __syncthreads();
    }
#pragma unroll
    for (int i = 0; i < 8; i++) {
        int gr = m0 + ty * 8 + i;
        if (gr < M) {
#pragma unroll
            for (int j = 0; j < 8; j += 4) {
                float4 v = make_float4(acc[i][j], acc[i][j + 1], acc[i][j + 2], acc[i][j + 3]);
                *(float4*)(Cp + (size_t)gr * ldc + colOff + tx * 8 + j) = v;
            }
        }
    }
}

// ---------------- edge aggregation: agg[dst] += w * Yn[src], C = 128 or 256 ----------------
template <int C>
__global__ void edge_agg(const int* __restrict__ src, const int* __restrict__ dst,
                         const float* __restrict__ ew,
                         const float* __restrict__ Yn, float* __restrict__ agg)
{
    int w = (blockIdx.x * blockDim.x + threadIdx.x) >> 5;
    if (w >= N_EDGES) return;
    int lane = threadIdx.x & 31;
    int s = src[w];
    int d = dst[w];
    float wt = ew[w];
    const float4* yp = (const float4*)(Yn + (size_t)s * C);
    float* ap = agg + (size_t)d * C;
#pragma unroll
    for (int c = 0; c < C / 128; c++) {
        int col = c * 32 + lane;
        float4 v = __ldg(&yp[col]);
        asm volatile("red.global.add.v4.f32 [%0], {%1,%2,%3,%4};"
                     :: "l"(ap + (size_t)col * 4),
                        "f"(v.x * wt), "f"(v.y * wt), "f"(v.z * wt), "f"(v.w * wt)
                     : "memory");
    }
}

// ---------------- gate r,u: r=sig(S_r+A_r+b_r), u=sig(S_u+A_u+b_u); RH=r*h; U=u ----------------
__global__ void gates_ru(const float* __restrict__ S1, const float* __restrict__ A1g,
                         const float* __restrict__ br, const float* __restrict__ bu,
                         const float* __restrict__ h,
                         float* __restrict__ RH, float* __restrict__ U)
{
    int idx = blockIdx.x * blockDim.x + threadIdx.x;
    if (idx >= NF) return;
    int i = idx >> 7;
    int f = idx & 127;
    float r = sigmoidf_(S1[(size_t)i * 256 + f] + A1g[(size_t)i * 256 + f] + __ldg(&br[f]));
    float u = sigmoidf_(S1[(size_t)i * 256 + 128 + f] + A1g[(size_t)i * 256 + 128 + f] + __ldg(&bu[f]));
    RH[idx] = r * h[idx];
    U[idx] = u;
}

// ---------------- finalize: c=sig(S_c+A_c+b_c); h' = u*h + (1-u)*c ----------------
__global__ void finalize(const float* __restrict__ S2, const float* __restrict__ A2g,
                         const float* __restrict__ bc,
                         const float* __restrict__ h, const float* __restrict__ U,
                         float* __restrict__ out_layer, float* __restrict__ out_extra)
{
    int idx = blockIdx.x * blockDim.x + threadIdx.x;
    if (idx >= NF) return;
    int f = idx & 127;
    float c = sigmoidf_(S2[idx] + A2g[idx] + __ldg(&bc[f]));
    float u = U[idx];
    float hn = u * h[idx] + (1.0f - u) * c;
    out_layer[idx] = hn;
    if (out_extra) out_extra[idx] = hn;
}

// ---------------- launch ----------------
extern "C" void kernel_launch(void* const* d_in, const int* in_sizes, int n_in,
                              void* d_out, int out_size)
{
    const float* x0   = (const float*)d_in[0];   // [N,128]
    const float* hst  = (const float*)d_in[1];   // [2,N,128]
    const int*   src  = (const int*)d_in[2];     // [E]
    const int*   dst  = (const int*)d_in[3];     // [E]
    const float* ew   = (const float*)d_in[4];   // [E]
    const float* Ws   = (const float*)d_in[5];   // [2,3,256,128]
    const float* Wn   = (const float*)d_in[6];   // [2,3,256,128]
    const float* bias = (const float*)d_in[7];   // [2,3,128]
    float* out = (float*)d_out;                  // [x | h0 | h1], each N*128

    float *S1, *Yn1, *A1g, *S2, *Yn2, *A2g, *RH, *U;
    cudaGetSymbolAddress((void**)&S1,  g_S1);
    cudaGetSymbolAddress((void**)&Yn1, g_Yn1);
    cudaGetSymbolAddress((void**)&A1g, g_AGG1);
    cudaGetSymbolAddress((void**)&S2,  g_S2);
    cudaGetSymbolAddress((void**)&Yn2, g_Yn2);
    cudaGetSymbolAddress((void**)&A2g, g_AGG2);
    cudaGetSymbolAddress((void**)&RH,  g_RH);
    cudaGetSymbolAddress((void**)&U,   g_U);

    const int mtiles = (N_NODES + 127) / 128;       // 391
    const int ew_blocks = (N_EDGES * 32 + 255) / 256; // warp per edge
    const int el_blocks = (NF + 255) / 256;

    for (int l = 0; l < 2; l++) {
        const float* xl = (l == 0) ? x0 : (out + NF);       // layer-1 input = h0
        const float* hl = hst + (size_t)l * NF;
        const float* Ws_l = Ws + (size_t)l * 3 * GSZ;
        const float* Wn_l = Wn + (size_t)l * 3 * GSZ;
        const float* b_r = bias + ((size_t)l * 3 + 0) * 128;
        const float* b_u = bias + ((size_t)l * 3 + 1) * 128;
        const float* b_c = bias + ((size_t)l * 3 + 2) * 128;

        // zero aggregation buffers
        zero_kernel<<<(N_NODES * 256 / 4 + 255) / 256, 256>>>(A1g, N_NODES * 256 / 4);
        zero_kernel<<<(N_NODES * 128 / 4 + 255) / 256, 256>>>(A2g, N_NODES * 128 / 4);

        // stage 1: [S_r|S_u] and [Yn_r|Yn_u]
        gemm_cat<<<dim3(mtiles, 4), 256>>>(xl, hl, Ws_l, Wn_l, 2, S1, Yn1, 256);
        edge_agg<256><<<ew_blocks, 256>>>(src, dst, ew, Yn1, A1g);
        gates_ru<<<el_blocks, 256>>>(S1, A1g, b_r, b_u, hl, RH, U);

        // stage 2: S_c and Yn_c with xh2 = [x, r*h]
        gemm_cat<<<dim3(mtiles, 2), 256>>>(xl, RH, Ws_l + 2 * GSZ, Wn_l + 2 * GSZ, 1, S2, Yn2, 128);
        edge_agg<128><<<ew_blocks, 256>>>(src, dst, ew, Yn2, A2g);

        float* out_layer = out + (size_t)(l + 1) * NF;   // h0 at NF, h1 at 2NF
        float* out_extra = (l == 1) ? out : nullptr;     // final x duplicated at offset 0
        finalize<<<el_blocks, 256>>>(S2, A2g, b_c, hl, U, out_layer, out_extra);
    }
    (void)in_sizes; (void)n_in; (void)out_size;
}

// round 2
// speedup vs baseline: 1.0046x; 1.0046x over previous
#include <cuda_runtime.h>
#include <math.h>

#define N_NODES 50000
#define N_EDGES 800000
#define F 128
#define NF (N_NODES * F)
#define GSZ (256 * 128)   // one gate weight matrix [2F, F]
#define BK 32

// ---------------- static device scratch (no allocs allowed) ----------------
__device__ float g_S1[N_NODES * 256];   // [S_r | S_u]    self-projections
__device__ float g_Yn1[N_NODES * 256];  // [Yn_r | Yn_u]  neighbor-projections
__device__ float g_AGG1[N_NODES * 256]; // aggregated neighbor terms r,u
__device__ float g_S2[N_NODES * 128];   // S_c
__device__ float g_Yn2[N_NODES * 128];  // Yn_c
__device__ float g_AGG2[N_NODES * 128]; // aggregated neighbor term c
__device__ float g_RH[N_NODES * 128];   // r * h
__device__ float g_U[N_NODES * 128];    // u gate

// ---------------- utility ----------------
__global__ void zero_kernel(float* __restrict__ p, int n4) {
    int i = blockIdx.x * blockDim.x + threadIdx.x;
    if (i < n4) ((float4*)p)[i] = make_float4(0.f, 0.f, 0.f, 0.f);
}

__device__ __forceinline__ float sigmoidf_(float x) {
    return 1.0f / (1.0f + expf(-x));
}

// packed f32x2 FMA: d = a*b + d (two fp32 lanes per instruction)
__device__ __forceinline__ void fma2(unsigned long long& d,
                                     unsigned long long a,
                                     unsigned long long b) {
    asm("fma.rn.f32x2 %0, %1, %2, %0;" : "+l"(d) : "l"(a), "l"(b));
}
__device__ __forceinline__ unsigned long long bcast2(float x) {
    unsigned long long r;
    asm("mov.b64 %0, {%1, %1};" : "=l"(r) : "f"(x));
    return r;
}

// ---------------- SGEMM: C = concat(A0,A1) @ B, f32x2 packed FMA ----------------
// A0, A1: [M,128] row-major (concatenated along K -> K=256)
// B blocks: by < half -> Bself + by*GSZ, writes Cself at col by*128
//           else       -> Bneigh + (by-half)*GSZ, writes Cneigh at col (by-half)*128
// Tiles: 128x128, BK=32, 256 threads, 8x8 per thread (accum as 8x4 f32x2 pairs).
__global__ void __launch_bounds__(256, 2) gemm_cat(
    const float* __restrict__ A0, const float* __restrict__ A1,
    const float* __restrict__ Bself, const float* __restrict__ Bneigh,
    int half, float* __restrict__ Cself, float* __restrict__ Cneigh, int ldc)
{
    const int M = N_NODES;
    __shared__ float As[BK][128];
    __shared__ float Bs[BK][128];

    int m0 = blockIdx.x * 128;
    int by = blockIdx.y;
    const float* Bp;
    float* Cp;
    int colOff;
    if (by < half) { Bp = Bself + (size_t)by * GSZ;          Cp = Cself;  colOff = by * 128; }
    else           { Bp = Bneigh + (size_t)(by - half) * GSZ; Cp = Cneigh; colOff = (by - half) * 128; }

    int tid = threadIdx.x;
    int ty = tid >> 4, tx = tid & 15;

    unsigned long long acc[8][4];
#pragma unroll
    for (int i = 0; i < 8; i++)
#pragma unroll
        for (int j = 0; j < 4; j++) acc[i][j] = 0ULL;

    for (int k0 = 0; k0 < 256; k0 += BK) {
        const float* A = (k0 < 128) ? A0 : A1;
        int kk0 = k0 & 127;
        // load A tile 128xBK (transposed into As[k][m]); 1024 float4 chunks, 4/thread
#pragma unroll
        for (int c0 = 0; c0 < 4; c0++) {
            int c = tid + c0 * 256;       // 0..1023
            int row = c >> 3;             // 0..127
            int kc = (c & 7) * 4;         // 0..28
            int gr = m0 + row;
            float4 v = make_float4(0.f, 0.f, 0.f, 0.f);
            if (gr < M) v = *(const float4*)(A + (size_t)gr * 128 + kk0 + kc);
            As[kc + 0][row] = v.x; As[kc + 1][row] = v.y;
            As[kc + 2][row] = v.z; As[kc + 3][row] = v.w;
        }
        // load B tile BKx128; 1024 float4 chunks, 4/thread
#pragma unroll
        for (int c0 = 0; c0 < 4; c0++) {
            int c = tid + c0 * 256;
            int krow = c >> 5;            // 0..31
            int ncol = (c & 31) * 4;      // 0..124
            float4 v = *(const float4*)(Bp + (size_t)(k0 + krow) * 128 + ncol);
            *(float4*)&Bs[krow][ncol] = v;
        }
        __syncthreads();
#pragma unroll
        for (int kk = 0; kk < BK; kk++) {
            const float* ar = &As[kk][ty * 8];
            const unsigned long long* br = (const unsigned long long*)&Bs[kk][tx * 8];
            unsigned long long b2[4];
#pragma unroll
            for (int j = 0; j < 4; j++) b2[j] = br[j];
#pragma unroll
            for (int i = 0; i < 8; i++) {
                unsigned long long a2 = bcast2(ar[i]);
#pragma unroll
                for (int j = 0; j < 4; j++) fma2(acc[i][j], a2, b2[j]);
            }
        }
        __syncthreads();
    }
#pragma unroll
    for (int i = 0; i < 8; i++) {
        int gr = m0 + ty * 8 + i;
        if (gr < M) {
            unsigned long long* cp = (unsigned long long*)(Cp + (size_t)gr * ldc + colOff + tx * 8);
            ulonglong2 v0; v0.x = acc[i][0]; v0.y = acc[i][1];
            ulonglong2 v1; v1.x = acc[i][2]; v1.y = acc[i][3];
            *(ulonglong2*)(cp + 0) = v0;
            *(ulonglong2*)(cp + 2) = v1;
        }
    }
}

// ---------------- edge aggregation: agg[dst] += w * Yn[src], C = 128 or 256 ----------------
template <int C>
__global__ void edge_agg(const int* __restrict__ src, const int* __restrict__ dst,
                         const float* __restrict__ ew,
                         const float* __restrict__ Yn, float* __restrict__ agg)
{
    int w = (blockIdx.x * blockDim.x + threadIdx.x) >> 5;
    if (w >= N_EDGES) return;
    int lane = threadIdx.x & 31;
    int s = src[w];
    int d = dst[w];
    float wt = ew[w];
    const float4* yp = (const float4*)(Yn + (size_t)s * C);
    float* ap = agg + (size_t)d * C;
#pragma unroll
    for (int c = 0; c < C / 128; c++) {
        int col = c * 32 + lane;
        float4 v = __ldg(&yp[col]);
        asm volatile("red.global.add.v4.f32 [%0], {%1,%2,%3,%4};"
                     :: "l"(ap + (size_t)col * 4),
                        "f"(v.x * wt), "f"(v.y * wt), "f"(v.z * wt), "f"(v.w * wt)
                     : "memory");
    }
}

// ---------------- gate r,u: r=sig(S_r+A_r+b_r), u=sig(S_u+A_u+b_u); RH=r*h; U=u ----------------
__global__ void gates_ru(const float* __restrict__ S1, const float* __restrict__ A1g,
                         const float* __restrict__ br, const float* __restrict__ bu,
                         const float* __restrict__ h,
                         float* __restrict__ RH, float* __restrict__ U)
{
    int idx = blockIdx.x * blockDim.x + threadIdx.x;
    if (idx >= NF) return;
    int i = idx >> 7;
    int f = idx & 127;
    float r = sigmoidf_(S1[(size_t)i * 256 + f] + A1g[(size_t)i * 256 + f] + __ldg(&br[f]));
    float u = sigmoidf_(S1[(size_t)i * 256 + 128 + f] + A1g[(size_t)i * 256 + 128 + f] + __ldg(&bu[f]));
    RH[idx] = r * h[idx];
    U[idx] = u;
}

// ---------------- finalize: c=sig(S_c+A_c+b_c); h' = u*h + (1-u)*c ----------------
__global__ void finalize(const float* __restrict__ S2, const float* __restrict__ A2g,
                         const float* __restrict__ bc,
                         const float* __restrict__ h, const float* __restrict__ U,
                         float* __restrict__ out_layer, float* __restrict__ out_extra)
{
    int idx = blockIdx.x * blockDim.x + threadIdx.x;
    if (idx >= NF) return;
    int f = idx & 127;
    float c = sigmoidf_(S2[idx] + A2g[idx] + __ldg(&bc[f]));
    float u = U[idx];
    float hn = u * h[idx] + (1.0f - u) * c;
    out_layer[idx] = hn;
    if (out_extra) out_extra[idx] = hn;
}

// ---------------- launch ----------------
extern "C" void kernel_launch(void* const* d_in, const int* in_sizes, int n_in,
                              void* d_out, int out_size)
{
    const float* x0   = (const float*)d_in[0];   // [N,128]
    const float* hst  = (const float*)d_in[1];   // [2,N,128]
    const int*   src  = (const int*)d_in[2];     // [E]
    const int*   dst  = (const int*)d_in[3];     // [E]
    const float* ew   = (const float*)d_in[4];   // [E]
    const float* Ws   = (const float*)d_in[5];   // [2,3,256,128]
    const float* Wn   = (const float*)d_in[6];   // [2,3,256,128]
    const float* bias = (const float*)d_in[7];   // [2,3,128]
    float* out = (float*)d_out;                  // [x | h0 | h1], each N*128

    float *S1, *Yn1, *A1g, *S2, *Yn2, *A2g, *RH, *U;
    cudaGetSymbolAddress((void**)&S1,  g_S1);
    cudaGetSymbolAddress((void**)&Yn1, g_Yn1);
    cudaGetSymbolAddress((void**)&A1g, g_AGG1);
    cudaGetSymbolAddress((void**)&S2,  g_S2);
    cudaGetSymbolAddress((void**)&Yn2, g_Yn2);
    cudaGetSymbolAddress((void**)&A2g, g_AGG2);
    cudaGetSymbolAddress((void**)&RH,  g_RH);
    cudaGetSymbolAddress((void**)&U,   g_U);

    const int mtiles = (N_NODES + 127) / 128;       // 391
    const int ew_blocks = (N_EDGES * 32 + 255) / 256; // warp per edge
    const int el_blocks = (NF + 255) / 256;

    for (int l = 0; l < 2; l++) {
        const float* xl = (l == 0) ? x0 : (out + NF);       // layer-1 input = h0
        const float* hl = hst + (size_t)l * NF;
        const float* Ws_l = Ws + (size_t)l * 3 * GSZ;
        const float* Wn_l = Wn + (size_t)l * 3 * GSZ;
        const float* b_r = bias + ((size_t)l * 3 + 0) * 128;
        const float* b_u = bias + ((size_t)l * 3 + 1) * 128;
        const float* b_c = bias + ((size_t)l * 3 + 2) * 128;

        // zero aggregation buffers
        zero_kernel<<<(N_NODES * 256 / 4 + 255) / 256, 256>>>(A1g, N_NODES * 256 / 4);
        zero_kernel<<<(N_NODES * 128 / 4 + 255) / 256, 256>>>(A2g, N_NODES * 128 / 4);

        // stage 1: [S_r|S_u] and [Yn_r|Yn_u]
        gemm_cat<<<dim3(mtiles, 4), 256>>>(xl, hl, Ws_l, Wn_l, 2, S1, Yn1, 256);
        edge_agg<256><<<ew_blocks, 256>>>(src, dst, ew, Yn1, A1g);
        gates_ru<<<el_blocks, 256>>>(S1, A1g, b_r, b_u, hl, RH, U);

        // stage 2: S_c and Yn_c with xh2 = [x, r*h]
        gemm_cat<<<dim3(mtiles, 2), 256>>>(xl, RH, Ws_l + 2 * GSZ, Wn_l + 2 * GSZ, 1, S2, Yn2, 128);
        edge_agg<128><<<ew_blocks, 256>>>(src, dst, ew, Yn2, A2g);

        float* out_layer = out + (size_t)(l + 1) * NF;   // h0 at NF, h1 at 2NF
        float* out_extra = (l == 1) ? out : nullptr;     // final x duplicated at offset 0
        finalize<<<el_blocks, 256>>>(S2, A2g, b_c, hl, U, out_layer, out_extra);
    }
    (void)in_sizes; (void)n_in; (void)out_size;
}

// round 6
// speedup vs baseline: 1.6129x; 1.6054x over previous
#include <cuda_runtime.h>
#include <math.h>
#include <stdint.h>

#define N_NODES 50000
#define N_EDGES 800000
#define F 128
#define NF (N_NODES * F)
#define GSZ (256 * 128)   // one gate weight matrix [2F, F]

// ---------------- static device scratch (no allocs allowed) ----------------
__device__ float g_S1[N_NODES * 256];
__device__ float g_Yn1[N_NODES * 256];
__device__ float g_AGG1[N_NODES * 256];
__device__ float g_S2[N_NODES * 128];
__device__ float g_Yn2[N_NODES * 128];
__device__ float g_AGG2[N_NODES * 128];
__device__ float g_RH[N_NODES * 128];
__device__ float g_U[N_NODES * 128];
__device__ float g_WT[12 * GSZ];        // transposed tf32-rounded weights [128n x 256k]

// ---------------- helpers ----------------
__device__ __forceinline__ float sigmoidf_(float x) { return 1.0f / (1.0f + expf(-x)); }

__device__ __forceinline__ uint32_t smem_u32(const void* p) {
    uint32_t a;
    asm("{ .reg .u64 t; cvta.to.shared.u64 t, %1; cvt.u32.u64 %0, t; }" : "=r"(a) : "l"(p));
    return a;
}
__device__ __forceinline__ uint32_t to_tf32(float x) {
    uint32_t r;
    asm("cvt.rna.tf32.f32 %0, %1;" : "=r"(r) : "f"(x));
    return r;
}
__device__ __forceinline__ void cp16(uint32_t dst, const void* src, int srcsz) {
    asm volatile("cp.async.cg.shared.global [%0], [%1], 16, %2;"
                 :: "r"(dst), "l"(src), "r"(srcsz) : "memory");
}
#define CP_COMMIT() asm volatile("cp.async.commit_group;" ::: "memory")
#define CP_WAIT(n)  asm volatile("cp.async.wait_group %0;" :: "n"(n) : "memory")

__device__ __forceinline__ void mma_tf32(float& d0, float& d1, float& d2, float& d3,
                                         uint32_t a0, uint32_t a1, uint32_t a2, uint32_t a3,
                                         uint32_t b0, uint32_t b1) {
    asm volatile("mma.sync.aligned.m16n8k8.row.col.f32.tf32.tf32.f32 "
                 "{%0,%1,%2,%3}, {%4,%5,%6,%7}, {%8,%9}, {%0,%1,%2,%3};"
                 : "+f"(d0), "+f"(d1), "+f"(d2), "+f"(d3)
                 : "r"(a0), "r"(a1), "r"(a2), "r"(a3), "r"(b0), "r"(b1));
}

// ---------------- small kernels ----------------
__global__ void zero_kernel(float* __restrict__ p, int n4) {
    int i = blockIdx.x * blockDim.x + threadIdx.x;
    if (i < n4) ((float4*)p)[i] = make_float4(0.f, 0.f, 0.f, 0.f);
}

// transpose + tf32-round all 12 weight mats [256,128] -> [128,256]
__global__ void transpose_w(const float* __restrict__ Ws, const float* __restrict__ Wn,
                            float* __restrict__ WT) {
    int mat = blockIdx.y;                 // (l*2+sn)*3+g
    int l = mat / 6, sn = (mat / 3) & 1, g = mat % 3;
    const float* src = (sn ? Wn : Ws) + ((size_t)l * 3 + g) * GSZ;
    float* dst = WT + (size_t)mat * GSZ;
    int i = blockIdx.x * blockDim.x + threadIdx.x;
    if (i < GSZ) {
        int n = i >> 8; int k = i & 255;
        uint32_t t = to_tf32(src[k * 128 + n]);
        dst[i] = __uint_as_float(t);
    }
}

// ---------------- tensor-core GEMM via mma.sync tf32 ----------------
// C[m, colOff:colOff+128] = concat(A0,A1)[m, 0:256] @ WT_mat^T
// Block tile 128x128, K=256 in 8 chunks of 32. 256 thr = 8 warps, warp = 64x32.
#define TSTR 36                            // smem row stride (floats), conflict-free
#define TILE_B (128 * TSTR * 4)            // one tile buffer bytes (18432)

__global__ void __launch_bounds__(256) gemm_tc(
    const float* __restrict__ A0, const float* __restrict__ A1,
    const float* __restrict__ BTself, const float* __restrict__ BTneigh,
    int half, float* __restrict__ Cself, float* __restrict__ Cneigh, int ldc)
{
    extern __shared__ float smem[];
    float* sA[2] = { smem,                smem + 128 * TSTR };
    float* sB[2] = { smem + 2 * 128 * TSTR, smem + 3 * 128 * TSTR };
    uint32_t uA[2] = { smem_u32(sA[0]), smem_u32(sA[1]) };
    uint32_t uB[2] = { smem_u32(sB[0]), smem_u32(sB[1]) };

    int tid = threadIdx.x, wid = tid >> 5, lid = tid & 31;
    int lr = lid >> 2, lc = lid & 3;
    int m0 = blockIdx.x * 128;
    int by = blockIdx.y;
    const float* BT; float* Cp; int colOff;
    if (by < half) { BT = BTself + (size_t)by * GSZ;           Cp = Cself;  colOff = by * 128; }
    else           { BT = BTneigh + (size_t)(by - half) * GSZ; Cp = Cneigh; colOff = (by - half) * 128; }

    int wm = wid & 1, wn = wid >> 1;       // warp tile: rows 64*wm, cols 32*wn

    float acc[4][4][4];
#pragma unroll
    for (int mt = 0; mt < 4; mt++)
#pragma unroll
        for (int nt = 0; nt < 4; nt++)
#pragma unroll
            for (int j = 0; j < 4; j++) acc[mt][nt][j] = 0.f;

    auto copy_tile = [&](int kt, int b) {
        const float* A = (kt < 4) ? A0 : A1;
        int kb = (kt & 3) * 32;
#pragma unroll
        for (int i = 0; i < 4; i++) {
            int c = tid + i * 256;         // 0..1023
            int row = c >> 3, q = c & 7;   // 8 x float4 per row
            int gr = m0 + row;
            int sz = (gr < N_NODES) ? 16 : 0;
            cp16(uA[b] + (uint32_t)(row * TSTR + q * 4) * 4,
                 A + (size_t)gr * 128 + kb + q * 4, sz);
            cp16(uB[b] + (uint32_t)(row * TSTR + q * 4) * 4,
                 BT + (size_t)row * 256 + kt * 32 + q * 4, 16);
        }
    };

    copy_tile(0, 0);
    CP_COMMIT();

    for (int kt = 0; kt < 8; kt++) {
        int b = kt & 1;
        if (kt < 7) { copy_tile(kt + 1, b ^ 1); CP_COMMIT(); CP_WAIT(1); }
        else        { CP_WAIT(0); }
        __syncthreads();

        const float* As = sA[b];
        const float* Bs = sB[b];
#pragma unroll
        for (int k8 = 0; k8 < 4; k8++) {
            int k0 = k8 * 8;
            // B fragments for 4 n-subtiles (weights pre-rounded to tf32)
            uint32_t bf[4][2];
#pragma unroll
            for (int nt = 0; nt < 4; nt++) {
                int nb = 32 * wn + 8 * nt + lr;
                bf[nt][0] = __float_as_uint(Bs[nb * TSTR + k0 + lc]);
                bf[nt][1] = __float_as_uint(Bs[nb * TSTR + k0 + lc + 4]);
            }
#pragma unroll
            for (int mt = 0; mt < 4; mt++) {
                int rb = 64 * wm + 16 * mt;
                uint32_t a0 = to_tf32(As[(rb + lr) * TSTR + k0 + lc]);
                uint32_t a1 = to_tf32(As[(rb + 8 + lr) * TSTR + k0 + lc]);
                uint32_t a2 = to_tf32(As[(rb + lr) * TSTR + k0 + lc + 4]);
                uint32_t a3 = to_tf32(As[(rb + 8 + lr) * TSTR + k0 + lc + 4]);
#pragma unroll
                for (int nt = 0; nt < 4; nt++)
                    mma_tf32(acc[mt][nt][0], acc[mt][nt][1], acc[mt][nt][2], acc[mt][nt][3],
                             a0, a1, a2, a3, bf[nt][0], bf[nt][1]);
            }
        }
        __syncthreads();
    }

    // epilogue: c0,c1 at (row, 2*lc), c2,c3 at (row+8, 2*lc)
#pragma unroll
    for (int mt = 0; mt < 4; mt++) {
        int r0 = m0 + 64 * wm + 16 * mt + lr;
#pragma unroll
        for (int nt = 0; nt < 4; nt++) {
            int col = colOff + 32 * wn + 8 * nt + 2 * lc;
            if (r0 < N_NODES)
                *(float2*)(Cp + (size_t)r0 * ldc + col) =
                    make_float2(acc[mt][nt][0], acc[mt][nt][1]);
            if (r0 + 8 < N_NODES)
                *(float2*)(Cp + (size_t)(r0 + 8) * ldc + col) =
                    make_float2(acc[mt][nt][2], acc[mt][nt][3]);
        }
    }
}

// ---------------- edge aggregation: agg[dst] += w * Yn[src] ----------------
template <int C>
__global__ void edge_agg(const int* __restrict__ src, const int* __restrict__ dst,
                         const float* __restrict__ ew,
                         const float* __restrict__ Yn, float* __restrict__ agg)
{
    int w = (blockIdx.x * blockDim.x + threadIdx.x) >> 5;
    if (w >= N_EDGES) return;
    int lane = threadIdx.x & 31;
    int s = src[w];
    int d = dst[w];
    float wt = ew[w];
    const float4* yp = (const float4*)(Yn + (size_t)s * C);
    float* ap = agg + (size_t)d * C;
#pragma unroll
    for (int c = 0; c < C / 128; c++) {
        int col = c * 32 + lane;
        float4 v = __ldg(&yp[col]);
        asm volatile("red.global.add.v4.f32 [%0], {%1,%2,%3,%4};"
                     :: "l"(ap + (size_t)col * 4),
                        "f"(v.x * wt), "f"(v.y * wt), "f"(v.z * wt), "f"(v.w * wt)
                     : "memory");
    }
}

// ---------------- gates ----------------
__global__ void gates_ru(const float* __restrict__ S1, const float* __restrict__ A1g,
                         const float* __restrict__ br, const float* __restrict__ bu,
                         const float* __restrict__ h,
                         float* __restrict__ RH, float* __restrict__ U)
{
    int idx = blockIdx.x * blockDim.x + threadIdx.x;
    if (idx >= NF) return;
    int i = idx >> 7;
    int f = idx & 127;
    float r = sigmoidf_(S1[(size_t)i * 256 + f] + A1g[(size_t)i * 256 + f] + __ldg(&br[f]));
    float u = sigmoidf_(S1[(size_t)i * 256 + 128 + f] + A1g[(size_t)i * 256 + 128 + f] + __ldg(&bu[f]));
    RH[idx] = r * h[idx];
    U[idx] = u;
}

__global__ void finalize(const float* __restrict__ S2, const float* __restrict__ A2g,
                         const float* __restrict__ bc,
                         const float* __restrict__ h, const float* __restrict__ U,
                         float* __restrict__ out_layer, float* __restrict__ out_extra)
{
    int idx = blockIdx.x * blockDim.x + threadIdx.x;
    if (idx >= NF) return;
    int f = idx & 127;
    float c = sigmoidf_(S2[idx] + A2g[idx] + __ldg(&bc[f]));
    float u = U[idx];
    float hn = u * h[idx] + (1.0f - u) * c;
    out_layer[idx] = hn;
    if (out_extra) out_extra[idx] = hn;
}

// ---------------- launch ----------------
extern "C" void kernel_launch(void* const* d_in, const int* in_sizes, int n_in,
                              void* d_out, int out_size)
{
    const float* x0   = (const float*)d_in[0];
    const float* hst  = (const float*)d_in[1];
    const int*   src  = (const int*)d_in[2];
    const int*   dst  = (const int*)d_in[3];
    const float* ew   = (const float*)d_in[4];
    const float* Ws   = (const float*)d_in[5];
    const float* Wn   = (const float*)d_in[6];
    const float* bias = (const float*)d_in[7];
    float* out = (float*)d_out;

    float *S1, *Yn1, *A1g, *S2, *Yn2, *A2g, *RH, *U, *WT;
    cudaGetSymbolAddress((void**)&S1,  g_S1);
    cudaGetSymbolAddress((void**)&Yn1, g_Yn1);
    cudaGetSymbolAddress((void**)&A1g, g_AGG1);
    cudaGetSymbolAddress((void**)&S2,  g_S2);
    cudaGetSymbolAddress((void**)&Yn2, g_Yn2);
    cudaGetSymbolAddress((void**)&A2g, g_AGG2);
    cudaGetSymbolAddress((void**)&RH,  g_RH);
    cudaGetSymbolAddress((void**)&U,   g_U);
    cudaGetSymbolAddress((void**)&WT,  g_WT);

    const int SMEM_SZ = 4 * TILE_B;      // 73728 B: A/B double-buffered
    cudaFuncSetAttribute(gemm_tc, cudaFuncAttributeMaxDynamicSharedMemorySize, SMEM_SZ);

    const int mtiles = (N_NODES + 127) / 128;
    const int ew_blocks = (N_EDGES * 32 + 255) / 256;
    const int el_blocks = (NF + 255) / 256;

    transpose_w<<<dim3((GSZ + 255) / 256, 12), 256>>>(Ws, Wn, WT);

    for (int l = 0; l < 2; l++) {
        const float* xl = (l == 0) ? x0 : (out + NF);
        const float* hl = hst + (size_t)l * NF;
        const float* BTs = WT + (size_t)((l * 2 + 0) * 3) * GSZ;
        const float* BTn = WT + (size_t)((l * 2 + 1) * 3) * GSZ;
        const float* b_r = bias + ((size_t)l * 3 + 0) * 128;
        const float* b_u = bias + ((size_t)l * 3 + 1) * 128;
        const float* b_c = bias + ((size_t)l * 3 + 2) * 128;

        zero_kernel<<<(N_NODES * 256 / 4 + 255) / 256, 256>>>(A1g, N_NODES * 256 / 4);
        zero_kernel<<<(N_NODES * 128 / 4 + 255) / 256, 256>>>(A2g, N_NODES * 128 / 4);

        gemm_tc<<<dim3(mtiles, 4), 256, SMEM_SZ>>>(xl, hl, BTs, BTn, 2, S1, Yn1, 256);
        edge_agg<256><<<ew_blocks, 256>>>(src, dst, ew, Yn1, A1g);
        gates_ru<<<el_blocks, 256>>>(S1, A1g, b_r, b_u, hl, RH, U);

        gemm_tc<<<dim3(mtiles, 2), 256, SMEM_SZ>>>(xl, RH, BTs + 2 * GSZ, BTn + 2 * GSZ,
                                                   1, S2, Yn2, 128);
        edge_agg<128><<<ew_blocks, 256>>>(src, dst, ew, Yn2, A2g);

        float* out_layer = out + (size_t)(l + 1) * NF;
        float* out_extra = (l == 1) ? out : nullptr;
        finalize<<<el_blocks, 256>>>(S2, A2g, b_c, hl, U, out_layer, out_extra);
    }
    (void)in_sizes; (void)n_in; (void)out_size;
}